// round 2
// baseline (speedup 1.0000x reference)
#include <cuda_runtime.h>
#include <cuda_bf16.h>

// Problem constants (fixed by the reference):
//   N = 8192 points, scales s in {2,4,8,16}
//   M = {16000, 4000, 512, 64} voxels, C = {32, 64, 128, 256} channels
//   out = [8192, 480] fp32, col offsets {0, 32, 96, 224}
//   center = idx[:,1:] * (0.015*s) + (-0.48) + 0.5*(0.015*s)

#define NPTS   8192
#define NCENT  20576          // 16000 + 4000 + 512 + 64
#define PPW    4              // points per warp (register tile)
#define FULLM  0xffffffffu

// Precomputed voxel centers: {x, y, z, x^2+y^2+z^2}
__device__ float4 g_centers[NCENT];

__global__ void prep_centers(const int* __restrict__ i0, const int* __restrict__ i1,
                             const int* __restrict__ i2, const int* __restrict__ i3)
{
    int t = blockIdx.x * blockDim.x + threadIdx.x;
    if (t >= NCENT) return;
    const int* idx; int local; float ve;
    if (t < 16000)      { idx = i0; local = t;         ve = 0.015f * 2.0f;  }
    else if (t < 20000) { idx = i1; local = t - 16000; ve = 0.015f * 4.0f;  }
    else if (t < 20512) { idx = i2; local = t - 20000; ve = 0.015f * 8.0f;  }
    else                { idx = i3; local = t - 20512; ve = 0.015f * 16.0f; }
    const float off = -0.0075f * 64.0f;  // matches numpy (-0.5*UNIT)*VNUM
    float h = 0.5f * ve;
    float x = (float)idx[local * 4 + 1] * ve + off + h;
    float y = (float)idx[local * 4 + 2] * ve + off + h;
    float z = (float)idx[local * 4 + 3] * ve + off + h;
    g_centers[t] = make_float4(x, y, z, x * x + y * y + z * z);
}

// Lexicographic (distance, index) comparison: exact jax.lax.top_k tie-break
// (stable: lower index wins on equal distance — required because duplicate
// voxel indices produce bitwise-identical distances).
__device__ __forceinline__ bool better(float d, int i, float D, int I)
{
    return (d < D) || (d == D && i < I);
}

// Insert one (d,i) candidate into a sorted best-3 (ascending) with tie-break.
__device__ __forceinline__ void merge1(float d, int i,
                                       float& b0, int& q0,
                                       float& b1, int& q1,
                                       float& b2, int& q2)
{
    if (better(d, i, b2, q2)) {
        if (better(d, i, b1, q1)) {
            b2 = b1; q2 = q1;
            if (better(d, i, b0, q0)) { b1 = b0; q1 = q0; b0 = d; q0 = i; }
            else                      { b1 = d;  q1 = i; }
        } else { b2 = d; q2 = i; }
    }
}

__global__ __launch_bounds__(128)
void nn_interp_kernel(const float* __restrict__ points,
                      const float* __restrict__ fA, const float* __restrict__ fB,
                      const float* __restrict__ fC, const float* __restrict__ fD,
                      float* __restrict__ out)
{
    const int lane = threadIdx.x & 31;
    const int warp = blockIdx.x * (blockDim.x >> 5) + (threadIdx.x >> 5);
    const int p0   = warp * PPW;

    float px[PPW], py[PPW], pz[PPW], mx[PPW], my[PPW], mz[PPW];
#pragma unroll
    for (int j = 0; j < PPW; j++) {
        px[j] = points[(p0 + j) * 3 + 0];
        py[j] = points[(p0 + j) * 3 + 1];
        pz[j] = points[(p0 + j) * 3 + 2];
        mx[j] = -2.0f * px[j];
        my[j] = -2.0f * py[j];
        mz[j] = -2.0f * pz[j];
    }

    const float* Fs[4]  = { fA, fB, fC, fD };
    const int Mar[4]  = { 16000, 4000, 512, 64 };
    const int Base[4] = { 0, 16000, 20000, 20512 };
    const int Car[4]  = { 32, 64, 128, 256 };
    const int Coff[4] = { 0, 32, 96, 224 };

#pragma unroll
    for (int s = 0; s < 4; s++) {
        const int M = Mar[s], base = Base[s], C = Car[s], coff = Coff[s];

        float b0[PPW], b1[PPW], b2[PPW];
        int   q0[PPW], q1[PPW], q2[PPW];
        const float INF = __int_as_float(0x7f800000);
#pragma unroll
        for (int j = 0; j < PPW; j++) {
            b0[j] = b1[j] = b2[j] = INF;
            q0[j] = q1[j] = q2[j] = -1;
        }

        // Lane-split scan over centers. t = |c|^2 - 2 p.c  (= d^2 - |p|^2,
        // strictly monotone in d^2, ties preserved). Strict '<' keeps the
        // earliest (lowest) index on ties within a lane (lane indices ascend).
#pragma unroll 4
        for (int m = lane; m < M; m += 32) {
            float4 c = g_centers[base + m];
#pragma unroll
            for (int j = 0; j < PPW; j++) {
                float t = fmaf(c.x, mx[j], fmaf(c.y, my[j], fmaf(c.z, mz[j], c.w)));
                if (t < b2[j]) {
                    if (t < b1[j]) {
                        b2[j] = b1[j]; q2[j] = q1[j];
                        if (t < b0[j]) { b1[j] = b0[j]; q1[j] = q0[j]; b0[j] = t; q0[j] = m; }
                        else           { b1[j] = t; q1[j] = m; }
                    } else { b2[j] = t; q2[j] = m; }
                }
            }
        }

        // Butterfly all-reduce: every lane converges to the global top-3.
        // Partner triples always come from disjoint index sets, so sequential
        // sorted-insertion of the partner's 3 entries is exact.
#pragma unroll
        for (int off2 = 16; off2 > 0; off2 >>= 1) {
#pragma unroll
            for (int j = 0; j < PPW; j++) {
                float od0 = __shfl_xor_sync(FULLM, b0[j], off2);
                int   oi0 = __shfl_xor_sync(FULLM, q0[j], off2);
                float od1 = __shfl_xor_sync(FULLM, b1[j], off2);
                int   oi1 = __shfl_xor_sync(FULLM, q1[j], off2);
                float od2 = __shfl_xor_sync(FULLM, b2[j], off2);
                int   oi2 = __shfl_xor_sync(FULLM, q2[j], off2);
                merge1(od0, oi0, b0[j], q0[j], b1[j], q1[j], b2[j], q2[j]);
                merge1(od1, oi1, b0[j], q0[j], b1[j], q1[j], b2[j], q2[j]);
                merge1(od2, oi2, b0[j], q0[j], b1[j], q1[j], b2[j], q2[j]);
            }
        }

        // Finalize + gather. All lanes hold identical top-3; recompute the
        // EXACT d^2 for the winners (avoids cancellation error of the shifted
        // form in the 1/(d2+1e-8) weights), then warp-parallel channel gather.
        const float* F = Fs[s];
#pragma unroll
        for (int j = 0; j < PPW; j++) {
            int   ids[3] = { q0[j], q1[j], q2[j] };
            float ws[3];
            float sum = 0.0f;
#pragma unroll
            for (int k = 0; k < 3; k++) {
                float4 c = g_centers[base + ids[k]];
                float dx = px[j] - c.x, dy = py[j] - c.y, dz = pz[j] - c.z;
                float d2 = dx * dx + dy * dy + dz * dz;
                ws[k] = 1.0f / (d2 + 1e-8f);
                sum += ws[k];
            }
            float inv = 1.0f / sum;
            float w0 = ws[0] * inv, w1 = ws[1] * inv, w2 = ws[2] * inv;
            long r0 = (long)ids[0] * C, r1 = (long)ids[1] * C, r2 = (long)ids[2] * C;
            float* o = out + (long)(p0 + j) * 480 + coff;
            for (int c = lane; c < C; c += 32) {
                float v = w0 * F[r0 + c] + w1 * F[r1 + c] + w2 * F[r2 + c];
                o[c] = v;
            }
        }
    }
}

extern "C" void kernel_launch(void* const* d_in, const int* in_sizes, int n_in,
                              void* d_out, int out_size)
{
    // Identify inputs by element count (all distinct), robust to ordering:
    //   points 24576, batch 8192,
    //   idx1 64000 / feats1 512000, idx2 16000 / feats2 256000,
    //   idx3 2048  / feats3 65536,  idx4 256   / feats4 16384
    const float* points = nullptr;
    const float* feats[4] = { nullptr, nullptr, nullptr, nullptr };
    const int*   inds[4]  = { nullptr, nullptr, nullptr, nullptr };
    for (int i = 0; i < n_in; i++) {
        switch (in_sizes[i]) {
            case 24576:  points   = (const float*)d_in[i]; break;
            case 8192:   /* batch_ids, all zero, unused */ break;
            case 64000:  inds[0]  = (const int*)d_in[i];   break;
            case 512000: feats[0] = (const float*)d_in[i]; break;
            case 16000:  inds[1]  = (const int*)d_in[i];   break;
            case 256000: feats[1] = (const float*)d_in[i]; break;
            case 2048:   inds[2]  = (const int*)d_in[i];   break;
            case 65536:  feats[2] = (const float*)d_in[i]; break;
            case 256:    inds[3]  = (const int*)d_in[i];   break;
            case 16384:  feats[3] = (const float*)d_in[i]; break;
            default: break;
        }
    }

    float* out = (float*)d_out;

    prep_centers<<<(NCENT + 255) / 256, 256>>>(inds[0], inds[1], inds[2], inds[3]);

    const int warps  = NPTS / PPW;        // 2048
    const int blocks = warps / 4;         // 512 blocks of 128 threads
    nn_interp_kernel<<<blocks, 128>>>(points, feats[0], feats[1], feats[2], feats[3], out);
}

// round 3
// speedup vs baseline: 2.5488x; 2.5488x over previous
#include <cuda_runtime.h>
#include <cuda_bf16.h>

// Ops_GetPointFeat: 3-NN inverse-distance interpolation, 4 voxel scales.
//   N = 8192 points, M = {16000,4000,512,64}, C = {32,64,128,256}
//   out = [8192, 480] fp32, col offsets {0,32,96,224}
//
// Strategy: centers are grid-aligned (voxel idx IS the spatial cell), so bin
// scales 0,1 into a perfect hash grid (32^3 / 16^3) and find each point's
// exact top-3 by adaptive Chebyshev-shell expansion with a conservative
// plane-distance stop bound. Scales 2,3 (512/64 centers) brute-force.
// All distance math replicates the reference's fp32 op-for-op (no fma
// contraction) so near-tie selection matches jax.lax.top_k; ties broken
// lexicographically by (d2, index) = stable top_k semantics.

#define NPTS   8192
#define M0     16000
#define M1     4000
#define M2     512
#define M3     64
#define G0     32
#define G1     16
#define NC0    (G0*G0*G0)        // 32768
#define NC1    (G1*G1*G1)        // 4096
#define NCELLS (NC0+NC1)         // 36864
#define NBIN   (M0+M1)           // 20000

// ---------------- device scratch (no allocations allowed) ----------------
__device__ int    g_counts[NCELLS];
__device__ int    g_start [NCELLS];
__device__ int    g_cursor[NCELLS];
__device__ int    g_alloc[1];
__device__ float4 g_binned[NBIN];        // {x,y,z, bits(orig_idx)} scale0+1
__device__ float4 g_cent23[M2+M3];       // centers for scales 2,3
__device__ int    g_ridx[4*NPTS*3];      // per point per scale: 3 nbr rows
__device__ float  g_rw  [4*NPTS*3];      // per point per scale: 3 weights

__device__ __forceinline__ float fINF() { return __int_as_float(0x7f800000); }

// Exact reference center coordinate: ((idx*ve) + OFFSET) + 0.5*ve, all fp32 rn.
// OFFSET = -0.5*0.015f*64 : power-of-two scalings of 0.015f are exact.
__device__ __forceinline__ float ccoord(int i, float ve)
{
    const float OFF = -32.0f * 0.015f;
    return __fadd_rn(__fadd_rn(__fmul_rn((float)i, ve), OFF), __fmul_rn(0.5f, ve));
}

// Exact reference d2: ((dx^2 + dy^2) + dz^2), no fma contraction.
__device__ __forceinline__ float exact_d2(float px, float py, float pz,
                                          float cx, float cy, float cz)
{
    float dx = __fsub_rn(px, cx), dy = __fsub_rn(py, cy), dz = __fsub_rn(pz, cz);
    return __fadd_rn(__fadd_rn(__fmul_rn(dx, dx), __fmul_rn(dy, dy)),
                     __fmul_rn(dz, dz));
}

// Lexicographic (d2, idx): stable top_k tie-break (lower index wins).
__device__ __forceinline__ bool better(float d, int i, float D, int I)
{
    return (d < D) || (d == D && i < I);
}

__device__ __forceinline__ void insert3(float d, int i,
                                        float& b0, int& q0,
                                        float& b1, int& q1,
                                        float& b2, int& q2)
{
    if (better(d, i, b2, q2)) {
        if (better(d, i, b1, q1)) {
            b2 = b1; q2 = q1;
            if (better(d, i, b0, q0)) { b1 = b0; q1 = q0; b0 = d; q0 = i; }
            else                      { b1 = d;  q1 = i; }
        } else { b2 = d; q2 = i; }
    }
}

// ---------------- prep kernels ----------------
__global__ void k_zero()
{
    int t = blockIdx.x * blockDim.x + threadIdx.x;
    if (t < NCELLS) g_counts[t] = 0;
    if (t == 0) g_alloc[0] = 0;
}

__global__ void k_count(const int* __restrict__ i0, const int* __restrict__ i1)
{
    int t = blockIdx.x * blockDim.x + threadIdx.x;
    if (t >= NBIN) return;
    int cell;
    if (t < M0) {
        const int* p = i0 + t * 4;
        cell = (p[1] * G0 + p[2]) * G0 + p[3];
    } else {
        const int* p = i1 + (t - M0) * 4;
        cell = NC0 + (p[1] * G1 + p[2]) * G1 + p[3];
    }
    atomicAdd(&g_counts[cell], 1);
}

// Per-cell contiguous ranges via bump allocator; ordering between cells is
// irrelevant (comparator is a total order -> results order-independent).
__global__ void k_assign()
{
    int t = blockIdx.x * blockDim.x + threadIdx.x;
    if (t >= NCELLS) return;
    int c = g_counts[t];
    int s = 0;
    if (c > 0) s = atomicAdd(&g_alloc[0], c);
    g_start[t]  = s;
    g_cursor[t] = s;
}

__global__ void k_scatter(const int* __restrict__ i0, const int* __restrict__ i1,
                          const int* __restrict__ i2, const int* __restrict__ i3)
{
    int t = blockIdx.x * blockDim.x + threadIdx.x;
    if (t >= NBIN + M2 + M3) return;
    if (t < NBIN) {
        const int* p; float ve; int cell, orig;
        if (t < M0) {
            p = i0 + t * 4; ve = 0.015f * 2.0f; orig = t;
            cell = (p[1] * G0 + p[2]) * G0 + p[3];
        } else {
            p = i1 + (t - M0) * 4; ve = 0.015f * 4.0f; orig = t - M0;
            cell = NC0 + (p[1] * G1 + p[2]) * G1 + p[3];
        }
        float4 v = make_float4(ccoord(p[1], ve), ccoord(p[2], ve),
                               ccoord(p[3], ve), __int_as_float(orig));
        int pos = atomicAdd(&g_cursor[cell], 1);
        g_binned[pos] = v;
    } else {
        int t2 = t - NBIN;   // [0, 576): 0..511 scale2, 512..575 scale3
        const int* p; float ve;
        if (t2 < M2) { p = i2 + t2 * 4;        ve = 0.015f * 8.0f;  }
        else         { p = i3 + (t2 - M2) * 4; ve = 0.015f * 16.0f; }
        g_cent23[t2] = make_float4(ccoord(p[1], ve), ccoord(p[2], ve),
                                   ccoord(p[3], ve), 0.0f);
    }
}

// ---------------- search: exact top-3 per (point, scale) ----------------
__global__ __launch_bounds__(128)
void k_search(const float* __restrict__ pts)
{
    const int i = blockIdx.x * 128 + threadIdx.x;   // point
    const int s = blockIdx.y;                        // scale 0..3
    const float px = pts[i * 3 + 0];
    const float py = pts[i * 3 + 1];
    const float pz = pts[i * 3 + 2];

    float b0 = fINF(), b1 = fINF(), b2 = fINF();
    int   q0 = 0x7fffffff, q1 = 0x7fffffff, q2 = 0x7fffffff;

    if (s < 2) {
        const int   G   = (s == 0) ? G0 : G1;
        const float ve  = (s == 0) ? (0.015f * 2.0f) : (0.015f * 4.0f);
        const int   cb  = (s == 0) ? 0 : NC0;
        const float OFF = -32.0f * 0.015f;
        const float inv = 1.0f / ve;

        int ci = (int)floorf((px - OFF) * inv);
        int cj = (int)floorf((py - OFF) * inv);
        int ck = (int)floorf((pz - OFF) * inv);
        ci = min(G - 1, max(0, ci));
        cj = min(G - 1, max(0, cj));
        ck = min(G - 1, max(0, ck));

        for (int r = 0; ; ++r) {
            // scan Chebyshev shell r (clamped to grid)
            for (int dx = -r; dx <= r; ++dx) {
                int x = ci + dx;
                if ((unsigned)x >= (unsigned)G) continue;
                int ax = dx < 0 ? -dx : dx;
                for (int dy = -r; dy <= r; ++dy) {
                    int y = cj + dy;
                    if ((unsigned)y >= (unsigned)G) continue;
                    int ay = dy < 0 ? -dy : dy;
                    int step = (ax == r || ay == r) ? 1 : 2 * r;
                    if (step < 1) step = 1;
                    for (int dz = -r; dz <= r; dz += step) {
                        int z = ck + dz;
                        if ((unsigned)z >= (unsigned)G) continue;
                        int cell = cb + (x * G + y) * G + z;
                        int st  = g_start[cell];
                        int cnt = g_counts[cell];
                        for (int j = 0; j < cnt; ++j) {
                            float4 c = g_binned[st + j];
                            float d2 = exact_d2(px, py, pz, c.x, c.y, c.z);
                            insert3(d2, __float_as_int(c.w),
                                    b0, q0, b1, q1, b2, q2);
                        }
                    }
                }
            }
            // stop bound: any unscanned center is beyond one of the scanned
            // box's faces (by >= ve/2, since centers sit mid-cell).
            if (b2 < fINF()) {
                float dmin = fINF();
                if (ci - r > 0)     dmin = fminf(dmin, px - (OFF + (float)(ci - r)     * ve));
                if (ci + r < G - 1) dmin = fminf(dmin,      (OFF + (float)(ci + r + 1) * ve) - px);
                if (cj - r > 0)     dmin = fminf(dmin, py - (OFF + (float)(cj - r)     * ve));
                if (cj + r < G - 1) dmin = fminf(dmin,      (OFF + (float)(cj + r + 1) * ve) - py);
                if (ck - r > 0)     dmin = fminf(dmin, pz - (OFF + (float)(ck - r)     * ve));
                if (ck + r < G - 1) dmin = fminf(dmin,      (OFF + (float)(ck + r + 1) * ve) - pz);
                if (dmin == fINF()) break;                      // grid exhausted
                if (dmin > 0.0f && dmin * dmin > b2) break;     // certified
            }
            if (r >= G) break;  // safety net
        }
    } else {
        const int base = (s == 2) ? 0 : M2;
        const int M    = (s == 2) ? M2 : M3;
        for (int m = 0; m < M; ++m) {
            float4 c = g_cent23[base + m];
            float d2 = exact_d2(px, py, pz, c.x, c.y, c.z);
            insert3(d2, m, b0, q0, b1, q1, b2, q2);
        }
    }

    // reference-exact weights: recip = 1/(d2+1e-8); w = recip / sum(recip)
    float r0 = __fdiv_rn(1.0f, __fadd_rn(b0, 1e-8f));
    float r1 = __fdiv_rn(1.0f, __fadd_rn(b1, 1e-8f));
    float r2 = __fdiv_rn(1.0f, __fadd_rn(b2, 1e-8f));
    float sum = __fadd_rn(__fadd_rn(r0, r1), r2);

    int o = (s * NPTS + i) * 3;
    g_ridx[o + 0] = q0; g_ridx[o + 1] = q1; g_ridx[o + 2] = q2;
    g_rw[o + 0] = __fdiv_rn(r0, sum);
    g_rw[o + 1] = __fdiv_rn(r1, sum);
    g_rw[o + 2] = __fdiv_rn(r2, sum);
}

// ---------------- gather: warp per point, coalesced 480-ch row ----------------
__global__ __launch_bounds__(256)
void k_gather(const float* __restrict__ fA, const float* __restrict__ fB,
              const float* __restrict__ fC, const float* __restrict__ fD,
              float* __restrict__ out)
{
    const int warp = blockIdx.x * 8 + (threadIdx.x >> 5);
    const int lane = threadIdx.x & 31;
    const int i    = warp;                         // point
    const float* Fs[4]   = { fA, fB, fC, fD };
    const int    Cs[4]   = { 32, 64, 128, 256 };
    const int    Coff[4] = { 0, 32, 96, 224 };
    float* o = out + (size_t)i * 480;

#pragma unroll
    for (int s = 0; s < 4; ++s) {
        int b = (s * NPTS + i) * 3;
        int i0 = g_ridx[b], i1 = g_ridx[b + 1], i2 = g_ridx[b + 2];
        float w0 = g_rw[b], w1 = g_rw[b + 1], w2 = g_rw[b + 2];
        const float* F = Fs[s];
        const int C = Cs[s];
        const float* r0 = F + (size_t)i0 * C;
        const float* r1 = F + (size_t)i1 * C;
        const float* r2 = F + (size_t)i2 * C;
        float* oo = o + Coff[s];
        for (int c = lane; c < C; c += 32)
            oo[c] = w0 * r0[c] + w1 * r1[c] + w2 * r2[c];
    }
}

// ---------------- launch ----------------
extern "C" void kernel_launch(void* const* d_in, const int* in_sizes, int n_in,
                              void* d_out, int out_size)
{
    // Identify inputs by element count (all 10 distinct):
    const float* points = nullptr;
    const float* feats[4] = { nullptr, nullptr, nullptr, nullptr };
    const int*   inds[4]  = { nullptr, nullptr, nullptr, nullptr };
    for (int i = 0; i < n_in; i++) {
        switch (in_sizes[i]) {
            case 24576:  points   = (const float*)d_in[i]; break;
            case 8192:   /* batch_ids (all zero) */        break;
            case 64000:  inds[0]  = (const int*)d_in[i];   break;
            case 512000: feats[0] = (const float*)d_in[i]; break;
            case 16000:  inds[1]  = (const int*)d_in[i];   break;
            case 256000: feats[1] = (const float*)d_in[i]; break;
            case 2048:   inds[2]  = (const int*)d_in[i];   break;
            case 65536:  feats[2] = (const float*)d_in[i]; break;
            case 256:    inds[3]  = (const int*)d_in[i];   break;
            case 16384:  feats[3] = (const float*)d_in[i]; break;
            default: break;
        }
    }

    k_zero   <<<(NCELLS + 255) / 256, 256>>>();
    k_count  <<<(NBIN + 255) / 256, 256>>>(inds[0], inds[1]);
    k_assign <<<(NCELLS + 255) / 256, 256>>>();
    k_scatter<<<(NBIN + M2 + M3 + 255) / 256, 256>>>(inds[0], inds[1], inds[2], inds[3]);

    dim3 sg(NPTS / 128, 4);
    k_search <<<sg, 128>>>(points);

    k_gather <<<NPTS / 8, 256>>>(feats[0], feats[1], feats[2], feats[3],
                                 (float*)d_out);
}